// round 3
// baseline (speedup 1.0000x reference)
#include <cuda_runtime.h>
#include <cstdint>
#include <math.h>

#define T_STEPS 64
#define BATCH   64
#define HID     1024
#define VOC     32000
#define M2      128
#define TB      4096

typedef unsigned long long ull;

// ---------------- device scratch ----------------
__device__ float g_xpre[(size_t)TB * 3 * HID];   // layer-0 input projections (+bias)
__device__ float g_h1hist[(size_t)TB * HID];     // h[1] per step (decoder input)
__device__ float g_ha[M2 * HID];                 // h ping
__device__ float g_hb[M2 * HID];                 // h pong
__device__ float g_rh[M2 * HID];                 // r * h
__device__ float g_f[M2 * HID];                  // f gate
__device__ float g_WUr1[HID * HID];              // Wr1 + Ur1
__device__ float g_WUf1[HID * HID];              // Wf1 + Uf1
__device__ float g_brc[HID], g_bfc[HID], g_bhc[HID];
__device__ float g_part[(size_t)16 * M2 * 2048]; // split-K partials (max 16*128*1024 == 8*128*2048)
__device__ int   g_cnt[64];                      // arrival counters (self-resetting)

__device__ __forceinline__ float sigm(float x) { return 1.0f / (1.0f + expf(-x)); }

// -------- packed f32x2 primitives --------
__device__ __forceinline__ ull pk2(float x) {
    ull r; asm("mov.b64 %0, {%1, %1};" : "=l"(r) : "f"(x)); return r;
}
__device__ __forceinline__ void fm2(ull& d, ull a, ull b) {
    asm("fma.rn.f32x2 %0, %1, %2, %3;" : "=l"(d) : "l"(a), "l"(b), "l"(d));
}

// ---------------- f32x2 GEMM core, accumulators paired along N ----------------
// C[m][2*TN2 cols] += A[m][k] * W[n][k];  A rows via arow(m), W row-major stride ldw.
// acc[i][j] holds cols (tn*2*TN2 + 2j, +1) for row tm*TM+i.
template<int BM, int BN, int BK, int TM, int TN2, int NT, class AF>
__device__ __forceinline__ void gcore(AF arow, const float* __restrict__ Wb,
                                      int Klen, int ldw,
                                      ull (&acc)[TM][TN2], float* __restrict__ sm)
{
    const int tid = threadIdx.x;
    constexpr int KV  = BK / 4;
    constexpr int AIT = BM * BK / 4 / NT;
    constexpr int WIT = BN * BK / 4 / NT;
    static_assert(AIT * NT == BM * BK / 4, "A loader");
    static_assert(WIT * NT == BN * BK / 4, "W loader");

    float4 ar[AIT], wr[WIT];
    auto fetch = [&](int kt) {
        #pragma unroll
        for (int r = 0; r < AIT; r++) {
            int idx = r * NT + tid; int m = idx / KV, kk = (idx % KV) * 4;
            ar[r] = *(const float4*)(arow(m) + kt + kk);
        }
        #pragma unroll
        for (int r = 0; r < WIT; r++) {
            int idx = r * NT + tid; int n = idx / KV, kk = (idx % KV) * 4;
            wr[r] = *(const float4*)(Wb + (size_t)n * ldw + kt + kk);
        }
    };
    auto stos = [&](int buf) {
        float* As = sm + buf * BK * BM;
        float* Ws = sm + 2 * BK * BM + buf * BK * BN;
        #pragma unroll
        for (int r = 0; r < AIT; r++) {
            int idx = r * NT + tid; int m = idx / KV, kk = (idx % KV) * 4;
            As[(kk+0)*BM+m]=ar[r].x; As[(kk+1)*BM+m]=ar[r].y;
            As[(kk+2)*BM+m]=ar[r].z; As[(kk+3)*BM+m]=ar[r].w;
        }
        #pragma unroll
        for (int r = 0; r < WIT; r++) {
            int idx = r * NT + tid; int n = idx / KV, kk = (idx % KV) * 4;
            Ws[(kk+0)*BN+n]=wr[r].x; Ws[(kk+1)*BN+n]=wr[r].y;
            Ws[(kk+2)*BN+n]=wr[r].z; Ws[(kk+3)*BN+n]=wr[r].w;
        }
    };

    constexpr int NG = BN / (2 * TN2);
    const int tn = tid % NG, tm = tid / NG;

    fetch(0); stos(0); __syncthreads();

    for (int kt = 0; kt < Klen; kt += BK) {
        const int buf = (kt / BK) & 1;
        if (kt + BK < Klen) fetch(kt + BK);
        const float* As = sm + buf * BK * BM + tm * TM;
        const float* Ws = sm + 2 * BK * BM + buf * BK * BN + tn * (2 * TN2);
        #pragma unroll
        for (int k = 0; k < BK; k++) {
            float av[TM];
            #pragma unroll
            for (int q = 0; q < TM/4; q++)
                *(float4*)(av + 4*q) = *(const float4*)(As + k * BM + 4*q);
            ull wv[TN2];
            #pragma unroll
            for (int q = 0; q < TN2/2; q++) {
                ulonglong2 t2 = *(const ulonglong2*)(Ws + k * BN + 4*q);
                wv[2*q] = t2.x; wv[2*q+1] = t2.y;
            }
            #pragma unroll
            for (int i = 0; i < TM; i++) {
                ull a2 = pk2(av[i]);
                #pragma unroll
                for (int j = 0; j < TN2; j++) fm2(acc[i][j], wv[j], a2);
            }
        }
        if (kt + BK < Klen) stos(buf ^ 1);
        __syncthreads();
    }
}

// ---------------- setup kernels ----------------
__global__ void k_hinit(const float* __restrict__ hidden) {
    int i = blockIdx.x * blockDim.x + threadIdx.x;
    if (i < M2 * HID) g_ha[i] = hidden[i];
}
__global__ void k_hout(float* __restrict__ out) {
    int i = blockIdx.x * blockDim.x + threadIdx.x;
    if (i < M2 * HID) out[i] = g_ha[i];
}
__global__ void k_addw(const float* __restrict__ Wr1, const float* __restrict__ Ur1,
                       const float* __restrict__ Wf1, const float* __restrict__ Uf1,
                       const float* __restrict__ br1, const float* __restrict__ bur1,
                       const float* __restrict__ bf1, const float* __restrict__ buf1,
                       const float* __restrict__ bh1, const float* __restrict__ buh1) {
    int i = blockIdx.x * blockDim.x + threadIdx.x;
    if (i < HID * HID) {
        g_WUr1[i] = Wr1[i] + Ur1[i];
        g_WUf1[i] = Wf1[i] + Uf1[i];
    }
    if (i < HID) {
        g_brc[i] = br1[i] + bur1[i];
        g_bfc[i] = bf1[i] + buf1[i];
        g_bhc[i] = bh1[i] + buh1[i];
    }
}

// ---------------- precompute: xpre = gather(emb) @ [Wr0|Wf0|Wh0].T + bias ----------------
__global__ __launch_bounds__(256)
void k_pre(const int* __restrict__ tokens, const float* __restrict__ emb,
           const float* __restrict__ W0, const float* __restrict__ W1, const float* __restrict__ W2,
           const float* __restrict__ b0, const float* __restrict__ b1, const float* __restrict__ b2)
{
    constexpr int BM = 128, BN = 128, BK = 16, TM = 8, TN2 = 4, NT = 256;
    __shared__ __align__(16) float sm[2*BK*BM + 2*BK*BN];
    __shared__ int stok[BM];
    const int m0 = blockIdx.y * BM, n0 = blockIdx.x * BN;
    const int seg = n0 >> 10, nn0 = n0 & 1023;
    const float* W    = (seg == 0) ? W0 : (seg == 1) ? W1 : W2;
    const float* bias = (seg == 0) ? b0 : (seg == 1) ? b1 : b2;

    if (threadIdx.x < BM) stok[threadIdx.x] = tokens[m0 + threadIdx.x];
    __syncthreads();

    ull acc[TM][TN2] = {};
    auto arow = [&](int m) { return emb + (size_t)stok[m] * HID; };
    gcore<BM,BN,BK,TM,TN2,NT>(arow, W + (size_t)nn0 * HID, HID, HID, acc, sm);

    constexpr int NG = BN / (2*TN2);
    const int tn = threadIdx.x % NG, tm = threadIdx.x / NG;
    #pragma unroll
    for (int i = 0; i < TM; i++) {
        const int m = m0 + tm*TM + i;
        const int nl = tn * (2*TN2);
        float* dst = g_xpre + (size_t)m * (3*HID) + n0 + nl;
        #pragma unroll
        for (int q = 0; q < TN2/2; q++) {
            union { ull u[2]; float4 f; } cv;
            cv.u[0] = acc[i][2*q]; cv.u[1] = acc[i][2*q+1];
            float4 bb = *(const float4*)(bias + nn0 + nl + 4*q);
            cv.f.x += bb.x; cv.f.y += bb.y; cv.f.z += bb.z; cv.f.w += bb.w;
            ((float4*)dst)[q] = cv.f;
        }
    }
}

// ---------------- fused split-K step phases ----------------
// PHASE 0: gates0 (N=2048: r|f), A=g_ha, W=Ur0|Uf0; eps: sigma -> g_rh (r*ha) / g_f
// PHASE 1: hwup0  (N=1024),      A=g_rh, W=Uh0;     eps: tanh+update: g_hb = ha + f*(hw-ha)
// PHASE 2: gates1 (N=2048: r|f), A=g_hb, W=WUr1|WUf1; eps: sigma -> g_rh (r*hb) / g_f
// PHASE 3: cand+update1 (N=2048: seg0=Wh1@hb, seg1=Uh1@rh); eps over paired tiles:
//          hw=tanh(sum0+sum1+bhc), g_ha = hb + f*(hw-hb), stash h1hist
template<int KS, int N, int PHASE>
__global__ __launch_bounds__(128)
void k_step(int t, const float* __restrict__ W0, const float* __restrict__ W1,
            const float* __restrict__ b0, const float* __restrict__ b1)
{
    constexpr int BM = 128, BN = 64, BK = 16, TM = 8, TN2 = 4, NT = 128;
    constexpr int CH = HID / KS;
    __shared__ __align__(16) float sm[2*BK*BM + 2*BK*BN];

    const int nt = blockIdx.x, ks = blockIdx.y;
    const int n0 = nt * BN;
    const int seg = n0 >> 10, nn0 = n0 & 1023;
    const int kb = ks * CH;

    const float* W;
    const float* Abase;
    if (PHASE == 0)      { W = seg ? W1 : W0;                 Abase = g_ha; }
    else if (PHASE == 1) { W = W0;                             Abase = g_rh; }
    else if (PHASE == 2) { W = seg ? g_WUf1 : g_WUr1;          Abase = g_hb; }
    else                 { W = seg ? W1 : W0;                  Abase = seg ? g_rh : g_hb; }

    ull acc[TM][TN2] = {};
    auto arow = [&](int m) { return Abase + (size_t)m * HID + kb; };
    gcore<BM,BN,BK,TM,TN2,NT>(arow, W + (size_t)nn0 * HID + kb, CH, HID, acc, sm);

    // ---- store partials ----
    constexpr int NG = BN / (2*TN2);
    const int tn = threadIdx.x % NG, tm = threadIdx.x / NG;
    #pragma unroll
    for (int i = 0; i < TM; i++) {
        const int m = tm*TM + i;
        float* dst = g_part + ((size_t)ks * M2 + m) * N + n0 + tn * (2*TN2);
        union { ull u[2]; float4 f; } cv;
        cv.u[0] = acc[i][0]; cv.u[1] = acc[i][1]; ((float4*)dst)[0] = cv.f;
        cv.u[0] = acc[i][2]; cv.u[1] = acc[i][3]; ((float4*)dst)[1] = cv.f;
    }
    __threadfence();

    // ---- arrival counter: last CTA reduces + applies gate math ----
    constexpr int ARR  = (PHASE == 3) ? 2*KS : KS;
    const int cidx = (PHASE == 3) ? (48 + (nt & 15)) : nt;
    __shared__ int slast;
    if (threadIdx.x == 0)
        slast = (atomicAdd(&g_cnt[cidx], 1) == ARR - 1) ? 1 : 0;
    __syncthreads();
    if (!slast) return;
    __threadfence();

    const int m = threadIdx.x;           // 128 rows, one per thread
    const int b = m & (BATCH - 1);
    const int ncol0 = (PHASE == 3) ? ((nt & 15) * BN) : n0;

    #pragma unroll 4
    for (int nb = 0; nb < BN; nb += 4) {
        const int n = ncol0 + nb;
        float4 s = make_float4(0.f, 0.f, 0.f, 0.f);
        #pragma unroll
        for (int q = 0; q < KS; q++) {
            float4 p = *(const float4*)(g_part + ((size_t)q * M2 + m) * N + n);
            s.x += p.x; s.y += p.y; s.z += p.z; s.w += p.w;
            if (PHASE == 3) {
                float4 p2 = *(const float4*)(g_part + ((size_t)q * M2 + m) * N + HID + n);
                s.x += p2.x; s.y += p2.y; s.z += p2.z; s.w += p2.w;
            }
        }
        float v[4] = {s.x, s.y, s.z, s.w};
        #pragma unroll
        for (int c = 0; c < 4; c++) {
            const int ng = n + c, nn = ng & (HID - 1);
            const int idx = m * HID + nn;
            if (PHASE == 0) {
                const float xadd = g_xpre[((size_t)t * BATCH + b) * (3*HID) + ng];
                const float bias = seg ? b1[nn] : b0[nn];
                const float gte = sigm(v[c] + bias + xadd);
                if (seg == 0) g_rh[idx] = gte * g_ha[idx];
                else          g_f[idx]  = gte;
            } else if (PHASE == 1) {
                const float xadd = g_xpre[((size_t)t * BATCH + b) * (3*HID) + 2*HID + ng];
                const float hw = tanhf(v[c] + b0[ng] + xadd);
                const float h = g_ha[idx];
                g_hb[idx] = h + g_f[idx] * (hw - h);
            } else if (PHASE == 2) {
                if (seg == 0) { const float r = sigm(v[c] + g_brc[nn]); g_rh[idx] = r * g_hb[idx]; }
                else          { g_f[idx] = sigm(v[c] + g_bfc[nn]); }
            } else {
                const float hw = tanhf(v[c] + g_bhc[nn]);
                const float h = g_hb[idx];
                const float nh = h + g_f[idx] * (hw - h);
                g_ha[idx] = nh;
                if (m >= BATCH)
                    g_h1hist[((size_t)t * BATCH + (m - BATCH)) * HID + nn] = nh;
            }
        }
    }
    if (threadIdx.x == 0) g_cnt[cidx] = 0;   // self-reset for next use
}

// ---------------- decoder: logits = h1hist @ Wdec.T + bdec ----------------
__global__ __launch_bounds__(128)
void k_dec(const float* __restrict__ Wdec, const float* __restrict__ bdec,
           float* __restrict__ out)
{
    constexpr int BM = 128, BN = 128, BK = 16, TM = 8, TN2 = 8, NT = 128;
    __shared__ __align__(16) float sm[2*BK*BM + 2*BK*BN];
    const int m0 = blockIdx.y * BM, n0 = blockIdx.x * BN;

    ull acc[TM][TN2] = {};
    auto arow = [&](int m) { return g_h1hist + (size_t)(m0 + m) * HID; };
    gcore<BM,BN,BK,TM,TN2,NT>(arow, Wdec + (size_t)n0 * HID, HID, HID, acc, sm);

    constexpr int NG = BN / (2*TN2);   // 8
    const int tn = threadIdx.x % NG, tm = threadIdx.x / NG;
    #pragma unroll
    for (int i = 0; i < TM; i++) {
        const int m = m0 + tm*TM + i;
        const int n = n0 + tn * (2*TN2);
        float* dst = out + (size_t)m * VOC + n;
        #pragma unroll
        for (int q = 0; q < TN2/2; q++) {
            union { ull u[2]; float4 f; } cv;
            cv.u[0] = acc[i][2*q]; cv.u[1] = acc[i][2*q+1];
            float4 bb = *(const float4*)(bdec + n + 4*q);
            cv.f.x += bb.x; cv.f.y += bb.y; cv.f.z += bb.z; cv.f.w += bb.w;
            ((float4*)dst)[q] = cv.f;
        }
    }
}

// ---------------- launch ----------------
extern "C" void kernel_launch(void* const* d_in, const int* in_sizes, int n_in,
                              void* d_out, int out_size)
{
    const int*   tokens = (const int*)  d_in[0];
    const float* hidden = (const float*)d_in[1];
    const float* emb    = (const float*)d_in[2];
    const float* Wr     = (const float*)d_in[3];
    const float* br     = (const float*)d_in[4];
    const float* Wf     = (const float*)d_in[5];
    const float* bf     = (const float*)d_in[6];
    const float* Wh     = (const float*)d_in[7];
    const float* bh     = (const float*)d_in[8];
    const float* Ur     = (const float*)d_in[9];
    const float* bur    = (const float*)d_in[10];
    const float* Ufw    = (const float*)d_in[11];
    const float* bufw   = (const float*)d_in[12];
    const float* Uh     = (const float*)d_in[13];
    const float* buh    = (const float*)d_in[14];
    const float* Wdec   = (const float*)d_in[15];
    const float* bdec   = (const float*)d_in[16];
    float* out = (float*)d_out;

    const size_t HH = (size_t)HID * HID;

    k_hinit<<<(M2*HID + 1023) / 1024, 1024>>>(hidden);
    k_addw<<<(HID*HID + 255) / 256, 256>>>(Wr + HH, Ur + HH, Wf + HH, Ufw + HH,
                                           br + HID, bur + HID, bf + HID, bufw + HID,
                                           bh + HID, buh + HID);
    k_pre<<<dim3(3*HID/128, TB/128), 256>>>(tokens, emb, Wr, Wf, Wh, br, bf, bh);

    for (int t = 0; t < T_STEPS; t++) {
        k_step<8, 2048, 0><<<dim3(32,  8), 128>>>(t, Ur, Ufw, bur, bufw);
        k_step<16,1024, 1><<<dim3(16, 16), 128>>>(t, Uh, nullptr, buh, nullptr);
        k_step<8, 2048, 2><<<dim3(32,  8), 128>>>(t, nullptr, nullptr, nullptr, nullptr);
        k_step<8, 2048, 3><<<dim3(32,  8), 128>>>(t, Wh + HH, Uh + HH, nullptr, nullptr);
    }

    k_dec<<<dim3(VOC/128, TB/128), 128>>>(Wdec, bdec, out);

    const long long logits_elems = (long long)TB * VOC;
    if ((long long)out_size >= logits_elems + (long long)M2 * HID)
        k_hout<<<(M2*HID + 1023) / 1024, 1024>>>(out + logits_elems);
}